// round 13
// baseline (speedup 1.0000x reference)
#include <cuda_runtime.h>
#include <math.h>

// Problem constants (fixed shapes per reference)
#define B_DIM 16
#define K_DIM 64
#define H_DIM 96
#define W_DIM 96
#define HW    (H_DIM * W_DIM)            // 9216
#define MAPS  (B_DIM * K_DIM)            // 1024
#define DK_ELEMS ((size_t)MAPS * HW)     // 9,437,184 per stack
#define KP_ELEMS ((size_t)B_DIM * 3 * K_DIM * 2)  // 6144 per stack
#define Z_ELEMS  ((size_t)B_DIM * K_DIM)          // 1024 per stack

#define NTHREADS 384                     // 12 warps; 2304 float4 = 384 * 6
#define NIT      6

// Fused kernel (the two-kernel split was a measured loss: the separate decode
// kernel cost 11.7us of serialized low-occupancy latency; the in-block tail
// overlaps across 2048 independent blocks and is nearly free).
// Cache policy: input loads DEFAULT (75.5MB input fits the 126MB L2 and is
// re-read every graph replay -> steady-state L2 hits); output stores __stcs
// (evict-first: write-only stream, doesn't displace the resident input).
__global__ __launch_bounds__(NTHREADS, 4)
void dcm2kp_kernel(const float* __restrict__ Rk,
                   const float* __restrict__ tfRk,
                   float* __restrict__ out)
{
    const int bid = blockIdx.x;          // [0, 2048)
    const int s   = bid >> 10;           // stack: 0 = Rk, 1 = tf_Rk
    const int bk  = bid & 1023;          // map index within stack

    const float* __restrict__ in = (s ? tfRk : Rk) + (size_t)bk * HW;
    float* __restrict__ dkout = out + (size_t)s * DK_ELEMS + (size_t)bk * HW;

    const int t = threadIdx.x;

    const float4* __restrict__ in4 = reinterpret_cast<const float4*>(in);
    float4* __restrict__ out4 = reinterpret_cast<float4*>(dkout);

    // ---- Phase 1: batch ALL loads up front (MLP = 6 per thread) ----
    float4 v[NIT];
    #pragma unroll
    for (int it = 0; it < NIT; ++it) {
        v[it] = in4[t + it * NTHREADS];  // default policy: L2-resident across replays
    }

    // ---- Phase 2: sigmoid -> evict-first store -> accumulate ----
    float zs = 0.0f, kxs = 0.0f, kys = 0.0f;

    #pragma unroll
    for (int it = 0; it < NIT; ++it) {
        const int j = t + it * NTHREADS;     // float4 index, [0, 2304)
        const int e = j << 2;                // element index, [0, 9216)

        // fast sigmoid (MUFU EX2 + RCP); rel err ~5e-7, fine for 1e-3 tol
        const float d0 = 1.0f / (1.0f + __expf(-v[it].x));
        const float d1 = 1.0f / (1.0f + __expf(-v[it].y));
        const float d2 = 1.0f / (1.0f + __expf(-v[it].z));
        const float d3 = 1.0f / (1.0f + __expf(-v[it].w));

        __stcs(&out4[j], make_float4(d0, d1, d2, d3));  // write-only stream

        // 4 consecutive elements share the row (96 % 4 == 0, e % 4 == 0)
        const int h  = e / 96;
        const int w0 = e - h * 96;

        const float s4 = (d0 + d1) + (d2 + d3);
        zs  += s4;
        kxs += fmaf((float)w0, s4, d1 + 2.0f * d2 + 3.0f * d3);
        kys += (float)h * s4;
    }

    // ---- Phase 3: block reduction ----
    #pragma unroll
    for (int o = 16; o > 0; o >>= 1) {
        zs  += __shfl_down_sync(0xffffffffu, zs,  o);
        kxs += __shfl_down_sync(0xffffffffu, kxs, o);
        kys += __shfl_down_sync(0xffffffffu, kys, o);
    }

    __shared__ double sz[12], sx[12], sy[12];
    const int wid = t >> 5, lid = t & 31;
    if (lid == 0) { sz[wid] = (double)zs; sx[wid] = (double)kxs; sy[wid] = (double)kys; }
    __syncthreads();

    // ---- Phase 4: decode tail (thread 0; gather is an L2 hit now) ----
    if (t == 0) {
        double z = 0.0, x = 0.0, y = 0.0;
        #pragma unroll
        for (int i = 0; i < 12; ++i) { z += sz[i]; x += sx[i]; y += sy[i]; }

        // jnp.round == round-half-to-even == rintf (default rounding mode)
        const float xr = rintf((float)(x / z));
        const float yr = rintf((float)(y / z));

        int wi = (int)xr; wi = wi < 0 ? 0 : (wi > 95 ? 95 : wi);
        int hi = (int)yr; hi = hi < 0 ? 0 : (hi > 95 ? 95 : hi);

        // gathered d: precise sigmoid (trunc boundaries are sensitive)
        const float dg = 1.0f / (1.0f + expf(-in[hi * 96 + wi]));

        const int b = bk >> 6;   // bk / 64
        const int k = bk & 63;   // bk % 64

        float* __restrict__ kpbase = out + 2 * DK_ELEMS + (size_t)s * KP_ELEMS
                                   + (size_t)b * (3 * K_DIM * 2);
        float* __restrict__ zbase  = out + 2 * DK_ELEMS + 2 * KP_ELEMS
                                   + (size_t)s * Z_ELEMS;

        // kp
        kpbase[k * 2 + 0] = xr;
        kpbase[k * 2 + 1] = yr;
        // kp1 = trunc(kp + kp*d)
        kpbase[(K_DIM + k) * 2 + 0] = truncf(xr + xr * dg);
        kpbase[(K_DIM + k) * 2 + 1] = truncf(yr + yr * dg);
        // kp2 = trunc(kp - kp*d)
        kpbase[(2 * K_DIM + k) * 2 + 0] = truncf(xr - xr * dg);
        kpbase[(2 * K_DIM + k) * 2 + 1] = truncf(yr - yr * dg);

        zbase[b * K_DIM + k] = (float)z;
    }
}

extern "C" void kernel_launch(void* const* d_in, const int* in_sizes, int n_in,
                              void* d_out, int out_size)
{
    (void)in_sizes; (void)n_in; (void)out_size;
    const float* Rk   = (const float*)d_in[0];
    const float* tfRk = (const float*)d_in[1];
    float* out = (float*)d_out;

    dcm2kp_kernel<<<2 * MAPS, NTHREADS>>>(Rk, tfRk, out);
}

// round 14
// speedup vs baseline: 1.3324x; 1.3324x over previous
#include <cuda_runtime.h>
#include <math.h>

// Problem constants (fixed shapes per reference)
#define B_DIM 16
#define K_DIM 64
#define H_DIM 96
#define W_DIM 96
#define HW    (H_DIM * W_DIM)            // 9216
#define MAPS  (B_DIM * K_DIM)            // 1024
#define DK_ELEMS ((size_t)MAPS * HW)     // 9,437,184 per stack
#define KP_ELEMS ((size_t)B_DIM * 3 * K_DIM * 2)  // 6144 per stack
#define Z_ELEMS  ((size_t)B_DIM * K_DIM)          // 1024 per stack

#define NTHREADS 384                     // 12 warps; 2304 float4 = 384 * 6
#define NWARPS   12
#define NIT      6
#define MAPS_PER_BLK 4
#define GRID     (2 * MAPS / MAPS_PER_BLK)   // 512 blocks -> single wave at 4 blk/SM

// Single-wave persistent kernel: 512 blocks x 4 maps each (uniform work, no
// wave transitions, no tail-wave imbalance). Cache policy is the measured-best
// combo: __ldcs loads (streaming) + DEFAULT stores (the R13 flip measured
// 43.2us vs 28.2us for this config — both streams can't fit L2, default
// write-back wins).
// Map loop has NO internal __syncthreads (per-map partials go to distinct smem
// slots); one sync at the end, then threads 0..3 run the 4 decode tails in
// parallel.
__global__ __launch_bounds__(NTHREADS, 4)
void dcm2kp_kernel(const float* __restrict__ Rk,
                   const float* __restrict__ tfRk,
                   float* __restrict__ out)
{
    const int t   = threadIdx.x;
    const int wid = t >> 5, lid = t & 31;

    __shared__ double sz[MAPS_PER_BLK][NWARPS];
    __shared__ double sx[MAPS_PER_BLK][NWARPS];
    __shared__ double sy[MAPS_PER_BLK][NWARPS];

    #pragma unroll 1
    for (int mi = 0; mi < MAPS_PER_BLK; ++mi) {
        const int m  = blockIdx.x * MAPS_PER_BLK + mi;   // [0, 2048)
        const int s  = m >> 10;              // stack: 0 = Rk, 1 = tf_Rk
        const int bk = m & 1023;             // map index within stack

        const float* __restrict__ in = (s ? tfRk : Rk) + (size_t)bk * HW;
        float* __restrict__ dkout = out + (size_t)s * DK_ELEMS + (size_t)bk * HW;

        const float4* __restrict__ in4 = reinterpret_cast<const float4*>(in);
        float4* __restrict__ out4 = reinterpret_cast<float4*>(dkout);

        // ---- batch ALL loads up front (MLP = 6 per thread) ----
        float4 v[NIT];
        #pragma unroll
        for (int it = 0; it < NIT; ++it) {
            v[it] = __ldcs(&in4[t + it * NTHREADS]);   // streaming read
        }

        // ---- sigmoid -> default store -> accumulate ----
        float zs = 0.0f, kxs = 0.0f, kys = 0.0f;

        #pragma unroll
        for (int it = 0; it < NIT; ++it) {
            const int j = t + it * NTHREADS;     // float4 index, [0, 2304)
            const int e = j << 2;                // element index, [0, 9216)

            // fast sigmoid (MUFU EX2 + RCP); rel err ~5e-7, fine for 1e-3 tol
            const float d0 = 1.0f / (1.0f + __expf(-v[it].x));
            const float d1 = 1.0f / (1.0f + __expf(-v[it].y));
            const float d2 = 1.0f / (1.0f + __expf(-v[it].z));
            const float d3 = 1.0f / (1.0f + __expf(-v[it].w));

            out4[j] = make_float4(d0, d1, d2, d3);   // default write-back

            // 4 consecutive elements share the row (96 % 4 == 0, e % 4 == 0)
            const int h  = e / 96;
            const int w0 = e - h * 96;

            const float s4 = (d0 + d1) + (d2 + d3);
            zs  += s4;
            kxs += fmaf((float)w0, s4, d1 + 2.0f * d2 + 3.0f * d3);
            kys += (float)h * s4;
        }

        // ---- warp reduction -> per-map smem slot (no block sync needed) ----
        #pragma unroll
        for (int o = 16; o > 0; o >>= 1) {
            zs  += __shfl_down_sync(0xffffffffu, zs,  o);
            kxs += __shfl_down_sync(0xffffffffu, kxs, o);
            kys += __shfl_down_sync(0xffffffffu, kys, o);
        }
        if (lid == 0) {
            sz[mi][wid] = (double)zs;
            sx[mi][wid] = (double)kxs;
            sy[mi][wid] = (double)kys;
        }
    }

    __syncthreads();

    // ---- decode tails: threads 0..3 each handle one map (parallel gathers) ----
    if (t < MAPS_PER_BLK) {
        const int m  = blockIdx.x * MAPS_PER_BLK + t;
        const int s  = m >> 10;
        const int bk = m & 1023;

        double z = 0.0, x = 0.0, y = 0.0;
        #pragma unroll
        for (int i = 0; i < NWARPS; ++i) {
            z += sz[t][i]; x += sx[t][i]; y += sy[t][i];
        }

        // jnp.round == round-half-to-even == rintf (default rounding mode)
        const float xr = rintf((float)(x / z));
        const float yr = rintf((float)(y / z));

        int wi = (int)xr; wi = wi < 0 ? 0 : (wi > 95 ? 95 : wi);
        int hi = (int)yr; hi = hi < 0 ? 0 : (hi > 95 ? 95 : hi);

        const float* __restrict__ in = (s ? tfRk : Rk) + (size_t)bk * HW;
        // gathered d: precise sigmoid (trunc boundaries are sensitive)
        const float dg = 1.0f / (1.0f + expf(-in[hi * 96 + wi]));

        const int b = bk >> 6;   // bk / 64
        const int k = bk & 63;   // bk % 64

        float* __restrict__ kpbase = out + 2 * DK_ELEMS + (size_t)s * KP_ELEMS
                                   + (size_t)b * (3 * K_DIM * 2);
        float* __restrict__ zbase  = out + 2 * DK_ELEMS + 2 * KP_ELEMS
                                   + (size_t)s * Z_ELEMS;

        // kp
        kpbase[k * 2 + 0] = xr;
        kpbase[k * 2 + 1] = yr;
        // kp1 = trunc(kp + kp*d)
        kpbase[(K_DIM + k) * 2 + 0] = truncf(xr + xr * dg);
        kpbase[(K_DIM + k) * 2 + 1] = truncf(yr + yr * dg);
        // kp2 = trunc(kp - kp*d)
        kpbase[(2 * K_DIM + k) * 2 + 0] = truncf(xr - xr * dg);
        kpbase[(2 * K_DIM + k) * 2 + 1] = truncf(yr - yr * dg);

        zbase[b * K_DIM + k] = (float)z;
    }
}

extern "C" void kernel_launch(void* const* d_in, const int* in_sizes, int n_in,
                              void* d_out, int out_size)
{
    (void)in_sizes; (void)n_in; (void)out_size;
    const float* Rk   = (const float*)d_in[0];
    const float* tfRk = (const float*)d_in[1];
    float* out = (float*)d_out;

    dcm2kp_kernel<<<GRID, NTHREADS>>>(Rk, tfRk, out);
}

// round 16
// speedup vs baseline: 1.3548x; 1.0168x over previous
#include <cuda_runtime.h>
#include <math.h>
#include <stdint.h>

// Problem constants (fixed shapes per reference)
#define B_DIM 16
#define K_DIM 64
#define H_DIM 96
#define W_DIM 96
#define HW    (H_DIM * W_DIM)            // 9216
#define MAPS  (B_DIM * K_DIM)            // 1024
#define DK_ELEMS ((size_t)MAPS * HW)     // 9,437,184 per stack
#define KP_ELEMS ((size_t)B_DIM * 3 * K_DIM * 2)  // 6144 per stack
#define Z_ELEMS  ((size_t)B_DIM * K_DIM)          // 1024 per stack

#define NTHREADS 384                     // 12 warps; 2304 float4 = 384 * 6
#define NWARPS   12
#define NIT      6
#define MAP_BYTES (HW * 4)               // 36864 bytes per map

// One block per map (2048 blocks) — reverted from persistent multi-map (R14
// loss: serialized MLP bubbles at map boundaries). Loads stay __ldcs + batched
// (best measured). NEW: the write stream goes through SMEM and leaves the SM
// as ONE 36KB cp.async.bulk (UBLKCP/TMA path) per block:
//   - removes 6 STG.128/thread (12cyc issue each) + store wavefronts from L1tex
//   - presents the memory controller with large contiguous write bursts
//     (better mixed R/W turnaround than warp-interleaved 512B chunks)
//   - decode tail overlaps the in-flight bulk copy (issue -> decode -> wait)
__global__ __launch_bounds__(NTHREADS, 4)
void dcm2kp_kernel(const float* __restrict__ Rk,
                   const float* __restrict__ tfRk,
                   float* __restrict__ out)
{
    __shared__ __align__(16) float sd[HW];           // 36864 B sigmoid tile
    __shared__ double sz[NWARPS], sx[NWARPS], sy[NWARPS];

    const int bid = blockIdx.x;          // [0, 2048)
    const int s   = bid >> 10;           // stack: 0 = Rk, 1 = tf_Rk
    const int bk  = bid & 1023;          // map index within stack

    const float* __restrict__ in = (s ? tfRk : Rk) + (size_t)bk * HW;
    float* __restrict__ dkout = out + (size_t)s * DK_ELEMS + (size_t)bk * HW;

    const int t = threadIdx.x;

    const float4* __restrict__ in4 = reinterpret_cast<const float4*>(in);
    float4* __restrict__ sd4 = reinterpret_cast<float4*>(sd);

    // ---- Phase 1: batch ALL loads up front (MLP = 6 per thread) ----
    float4 v[NIT];
    #pragma unroll
    for (int it = 0; it < NIT; ++it) {
        v[it] = __ldcs(&in4[t + it * NTHREADS]);   // streaming read
    }

    // ---- Phase 2: sigmoid -> STS (smem tile) -> accumulate ----
    float zs = 0.0f, kxs = 0.0f, kys = 0.0f;

    #pragma unroll
    for (int it = 0; it < NIT; ++it) {
        const int j = t + it * NTHREADS;     // float4 index, [0, 2304)
        const int e = j << 2;                // element index, [0, 9216)

        // fast sigmoid (MUFU EX2 + RCP); rel err ~5e-7, fine for 1e-3 tol
        const float d0 = 1.0f / (1.0f + __expf(-v[it].x));
        const float d1 = 1.0f / (1.0f + __expf(-v[it].y));
        const float d2 = 1.0f / (1.0f + __expf(-v[it].z));
        const float d3 = 1.0f / (1.0f + __expf(-v[it].w));

        sd4[j] = make_float4(d0, d1, d2, d3);    // STS.128, conflict-free

        // 4 consecutive elements share the row (96 % 4 == 0, e % 4 == 0)
        const int h  = e / 96;
        const int w0 = e - h * 96;

        const float s4 = (d0 + d1) + (d2 + d3);
        zs  += s4;
        kxs += fmaf((float)w0, s4, d1 + 2.0f * d2 + 3.0f * d3);
        kys += (float)h * s4;
    }

    // ---- Phase 3: warp reduce -> smem partials ----
    #pragma unroll
    for (int o = 16; o > 0; o >>= 1) {
        zs  += __shfl_down_sync(0xffffffffu, zs,  o);
        kxs += __shfl_down_sync(0xffffffffu, kxs, o);
        kys += __shfl_down_sync(0xffffffffu, kys, o);
    }
    const int wid = t >> 5, lid = t & 31;
    if (lid == 0) { sz[wid] = (double)zs; sx[wid] = (double)kxs; sy[wid] = (double)kys; }
    __syncthreads();    // all STS (tile + partials) visible

    // ---- Phase 4: thread 0: bulk store + decode tail (overlapped) ----
    if (t == 0) {
        // make generic STS visible to the async proxy, then kick the 36KB copy
        asm volatile("fence.proxy.async.shared::cta;" ::: "memory");
        uint32_t src;
        asm("{ .reg .u64 a; cvta.to.shared.u64 a, %1; cvt.u32.u64 %0, a; }"
            : "=r"(src) : "l"((const void*)sd));
        asm volatile("cp.async.bulk.global.shared::cta.bulk_group [%0], [%1], %2;"
                     :: "l"(dkout), "r"(src), "r"((uint32_t)MAP_BYTES) : "memory");
        asm volatile("cp.async.bulk.commit_group;" ::: "memory");

        // decode while the copy flies
        double z = 0.0, x = 0.0, y = 0.0;
        #pragma unroll
        for (int i = 0; i < NWARPS; ++i) { z += sz[i]; x += sx[i]; y += sy[i]; }

        // jnp.round == round-half-to-even == rintf (default rounding mode)
        const float xr = rintf((float)(x / z));
        const float yr = rintf((float)(y / z));

        int wi = (int)xr; wi = wi < 0 ? 0 : (wi > 95 ? 95 : wi);
        int hi = (int)yr; hi = hi < 0 ? 0 : (hi > 95 ? 95 : hi);

        // gathered d: read from the smem tile (already sigmoid), but recompute
        // precisely from input for trunc-boundary safety
        const float dg = 1.0f / (1.0f + expf(-in[hi * 96 + wi]));

        const int b = bk >> 6;   // bk / 64
        const int k = bk & 63;   // bk % 64

        float* __restrict__ kpbase = out + 2 * DK_ELEMS + (size_t)s * KP_ELEMS
                                   + (size_t)b * (3 * K_DIM * 2);
        float* __restrict__ zbase  = out + 2 * DK_ELEMS + 2 * KP_ELEMS
                                   + (size_t)s * Z_ELEMS;

        // kp
        kpbase[k * 2 + 0] = xr;
        kpbase[k * 2 + 1] = yr;
        // kp1 = trunc(kp + kp*d)
        kpbase[(K_DIM + k) * 2 + 0] = truncf(xr + xr * dg);
        kpbase[(K_DIM + k) * 2 + 1] = truncf(yr + yr * dg);
        // kp2 = trunc(kp - kp*d)
        kpbase[(2 * K_DIM + k) * 2 + 0] = truncf(xr - xr * dg);
        kpbase[(2 * K_DIM + k) * 2 + 1] = truncf(yr - yr * dg);

        zbase[b * K_DIM + k] = (float)z;

        // CTA must not retire while the bulk copy still reads its smem
        asm volatile("cp.async.bulk.wait_group 0;" ::: "memory");
    }
}

extern "C" void kernel_launch(void* const* d_in, const int* in_sizes, int n_in,
                              void* d_out, int out_size)
{
    (void)in_sizes; (void)n_in; (void)out_size;
    const float* Rk   = (const float*)d_in[0];
    const float* tfRk = (const float*)d_in[1];
    float* out = (float*)d_out;

    dcm2kp_kernel<<<2 * MAPS, NTHREADS>>>(Rk, tfRk, out);
}